// round 14
// baseline (speedup 1.0000x reference)
#include <cuda_runtime.h>
#include <math.h>

#define NB   8
#define NL   4096
#define NDM  1024
#define NH   16
#define NDH  64
#define NU   45
#define NBH  (NB*NH)

// Scratch (device globals — allocation-free rule)
__device__ float g_q[(size_t)NBH*NL*NDH];   // [b][h][l][d]
__device__ float g_k[(size_t)NBH*NL*NDH];
__device__ float g_v[(size_t)NBH*NL*NDH];
__device__ float g_M[(size_t)NBH*NL];
__device__ int   g_top[NBH*NU];
__device__ float g_ctx[NBH*NDH];

// ---------------------------------------------------------------------------
// Projection SGEMM: C[r, j] = sum_c In[r,c] * W[j,c] + bias[j]
// In: (32768 x 1024) row-major, W: (1024 x 1024) row-major ("out" dim first).
// Output scattered into [b][h][l][d] layout. 128x128 tile, 16 k-step,
// 256 threads, 8x8 register micro-tile.
// blockIdx.z selects which projection (0=q,1=k,2=v).
// ---------------------------------------------------------------------------
__global__ __launch_bounds__(256, 2)
void proj_kernel(const float* __restrict__ Qin, const float* __restrict__ Kin,
                 const float* __restrict__ Vin,
                 const float* __restrict__ Wq, const float* __restrict__ bq,
                 const float* __restrict__ Wk, const float* __restrict__ bk,
                 const float* __restrict__ Wv, const float* __restrict__ bv)
{
    const float* In; const float* W; const float* bias; float* Out;
    if (blockIdx.z == 0)      { In = Qin; W = Wq; bias = bq; Out = g_q; }
    else if (blockIdx.z == 1) { In = Kin; W = Wk; bias = bk; Out = g_k; }
    else                      { In = Vin; W = Wv; bias = bv; Out = g_v; }

    __shared__ float As[16][128];
    __shared__ float Bs[16][128];

    const int row0 = blockIdx.y * 128;
    const int col0 = blockIdx.x * 128;
    const int tid  = threadIdx.x;
    const int ty   = tid >> 4;     // 0..15
    const int tx   = tid & 15;     // 0..15

    float acc[8][8];
#pragma unroll
    for (int i = 0; i < 8; i++)
#pragma unroll
        for (int j = 0; j < 8; j++) acc[i][j] = 0.f;

    for (int c0 = 0; c0 < NDM; c0 += 16) {
        // Load 128x16 tiles of A and W (transposed into smem: [c][row])
#pragma unroll
        for (int it = 0; it < 2; it++) {
            int s  = tid + it * 256;        // 0..511
            int r  = s >> 2;                // 0..127
            int cv = (s & 3) * 4;           // 0,4,8,12
            float4 a = *(const float4*)&In[(size_t)(row0 + r) * NDM + c0 + cv];
            As[cv + 0][r] = a.x; As[cv + 1][r] = a.y;
            As[cv + 2][r] = a.z; As[cv + 3][r] = a.w;
            float4 b = *(const float4*)&W[(size_t)(col0 + r) * NDM + c0 + cv];
            Bs[cv + 0][r] = b.x; Bs[cv + 1][r] = b.y;
            Bs[cv + 2][r] = b.z; Bs[cv + 3][r] = b.w;
        }
        __syncthreads();

#pragma unroll
        for (int c = 0; c < 16; c++) {
            float4 a0 = *(const float4*)&As[c][ty * 8];
            float4 a1 = *(const float4*)&As[c][ty * 8 + 4];
            float4 b0 = *(const float4*)&Bs[c][tx * 8];
            float4 b1 = *(const float4*)&Bs[c][tx * 8 + 4];
            float av[8] = {a0.x, a0.y, a0.z, a0.w, a1.x, a1.y, a1.z, a1.w};
            float bv2[8] = {b0.x, b0.y, b0.z, b0.w, b1.x, b1.y, b1.z, b1.w};
#pragma unroll
            for (int i = 0; i < 8; i++)
#pragma unroll
                for (int j = 0; j < 8; j++)
                    acc[i][j] = fmaf(av[i], bv2[j], acc[i][j]);
        }
        __syncthreads();
    }

    // Epilogue: scatter into [b][h][l][d]
#pragma unroll
    for (int i = 0; i < 8; i++) {
        int r = row0 + ty * 8 + i;
        int b_ = r >> 12;            // /4096
        int l  = r & (NL - 1);
#pragma unroll
        for (int j = 0; j < 8; j++) {
            int col = col0 + tx * 8 + j;
            int h = col >> 6;
            int d = col & 63;
            Out[(((size_t)(b_ * NH + h)) * NL + l) * NDH + d] = acc[i][j] + bias[col];
        }
    }
}

// ---------------------------------------------------------------------------
// M kernel: per (b,h,query) compute qk against 45 sampled keys, M = max - mean
// ---------------------------------------------------------------------------
__global__ __launch_bounds__(256)
void m_kernel(const int* __restrict__ idx)
{
    const int bh = blockIdx.y;
    __shared__ float ks[NU][NDH];

    for (int t = threadIdx.x; t < NU * NDH; t += 256) {
        int j = t >> 6, d = t & 63;
        int key = idx[j];
        ks[j][d] = g_k[((size_t)bh * NL + key) * NDH + d];
    }
    __syncthreads();

    const int i = blockIdx.x * 256 + threadIdx.x;
    const float* qp = &g_q[((size_t)bh * NL + i) * NDH];
    float q[NDH];
#pragma unroll
    for (int d = 0; d < NDH; d += 4) {
        float4 t4 = *(const float4*)&qp[d];
        q[d] = t4.x; q[d + 1] = t4.y; q[d + 2] = t4.z; q[d + 3] = t4.w;
    }

    float mx = -INFINITY, sum = 0.f;
    for (int j = 0; j < NU; j++) {
        float s = 0.f;
#pragma unroll
        for (int d = 0; d < NDH; d++) s = fmaf(q[d], ks[j][d], s);
        mx = fmaxf(mx, s);
        sum += s;
    }
    g_M[(size_t)bh * NL + i] = mx - sum * (1.0f / NU);
}

// ---------------------------------------------------------------------------
// Top-45 per (b,h): iterative argmax over 4096 with lowest-index tie break.
// Also zeroes g_ctx for this (b,h).
// ---------------------------------------------------------------------------
__global__ __launch_bounds__(256)
void topk_kernel()
{
    const int bh = blockIdx.x;
    const int tid = threadIdx.x;
    __shared__ float sm[NL];
    __shared__ float rv[256];
    __shared__ int   ri[256];

    if (tid < NDH) g_ctx[bh * NDH + tid] = 0.f;

    for (int t = tid; t < NL; t += 256) sm[t] = g_M[(size_t)bh * NL + t];
    __syncthreads();

    for (int it = 0; it < NU; it++) {
        float best = -INFINITY;
        int bidx = NL;
        for (int t = tid; t < NL; t += 256) {
            float v = sm[t];
            if (v > best) { best = v; bidx = t; }
        }
        rv[tid] = best; ri[tid] = bidx;
        __syncthreads();
        for (int off = 128; off > 0; off >>= 1) {
            if (tid < off) {
                float v2 = rv[tid + off]; int i2 = ri[tid + off];
                if (v2 > rv[tid] || (v2 == rv[tid] && i2 < ri[tid])) {
                    rv[tid] = v2; ri[tid] = i2;
                }
            }
            __syncthreads();
        }
        if (tid == 0) {
            g_top[bh * NU + it] = ri[0];
            sm[ri[0]] = -INFINITY;
        }
        __syncthreads();
    }
}

// ---------------------------------------------------------------------------
// Attention kernel: one block per (b,h,u). Full softmax over 4096 keys,
// ctx accumulated into g_ctx (sum with 1/45 factor).
// ---------------------------------------------------------------------------
__global__ __launch_bounds__(256)
void attn_kernel()
{
    const int bh = blockIdx.y;
    const int u  = blockIdx.x;
    const int tid = threadIdx.x;

    __shared__ float sc[NL];     // 16 KB
    __shared__ float qs[NDH];
    __shared__ float red[256];

    const int qi = g_top[bh * NU + u];
    if (tid < NDH) qs[tid] = g_q[((size_t)bh * NL + qi) * NDH + tid];
    __syncthreads();

    const float* kb = &g_k[(size_t)bh * NL * NDH];
    for (int key = tid; key < NL; key += 256) {
        const float* kr = &kb[key * NDH];
        float s = 0.f;
#pragma unroll
        for (int d = 0; d < NDH; d += 4) {
            float4 k4 = *(const float4*)&kr[d];
            s = fmaf(k4.x, qs[d], s);
            s = fmaf(k4.y, qs[d + 1], s);
            s = fmaf(k4.z, qs[d + 2], s);
            s = fmaf(k4.w, qs[d + 3], s);
        }
        sc[key] = s * 0.125f;    // 1/sqrt(64)
    }
    __syncthreads();

    // max
    float mx = -INFINITY;
    for (int key = tid; key < NL; key += 256) mx = fmaxf(mx, sc[key]);
    red[tid] = mx; __syncthreads();
    for (int off = 128; off > 0; off >>= 1) {
        if (tid < off) red[tid] = fmaxf(red[tid], red[tid + off]);
        __syncthreads();
    }
    mx = red[0];
    __syncthreads();

    // exp + sum
    float sum = 0.f;
    for (int key = tid; key < NL; key += 256) {
        float e = __expf(sc[key] - mx);
        sc[key] = e;
        sum += e;
    }
    red[tid] = sum; __syncthreads();
    for (int off = 128; off > 0; off >>= 1) {
        if (tid < off) red[tid] += red[tid + off];
        __syncthreads();
    }
    const float inv = 1.0f / red[0];
    __syncthreads();

    // ctx: thread (g, d), g in 0..3, d in 0..63
    const int d = tid & 63;
    const int g = tid >> 6;
    const float* vb = &g_v[(size_t)bh * NL * NDH];
    float acc = 0.f;
    for (int key = g; key < NL; key += 4)
        acc = fmaf(sc[key], vb[(size_t)key * NDH + d], acc);
    red[tid] = acc;
    __syncthreads();
    if (g == 0) {
        float tot = red[d] + red[64 + d] + red[128 + d] + red[192 + d];
        atomicAdd(&g_ctx[bh * NDH + d], tot * inv * (1.0f / NU));
    }
}

// ---------------------------------------------------------------------------
// Output projection: out[b,o] = sum_m ctx_flat[b,m] * Wo[o,m] + bo[o]
// ctx_flat[b, d*16 + h] = g_ctx[(b*16+h)*64 + d]   (transpose(0,2,1).reshape)
// ---------------------------------------------------------------------------
__global__ __launch_bounds__(256)
void outproj_kernel(const float* __restrict__ Wo, const float* __restrict__ bo,
                    float* __restrict__ out)
{
    const int b = blockIdx.y;
    const int o = blockIdx.x * 256 + threadIdx.x;
    __shared__ float cf[NDM];

    for (int t = threadIdx.x; t < NDM; t += 256) {
        int d = t >> 4;      // m = d*16 + h
        int h = t & 15;
        cf[t] = g_ctx[(b * NH + h) * NDH + d];
    }
    __syncthreads();

    float acc = bo[o];
    const float* wr = &Wo[(size_t)o * NDM];
#pragma unroll 4
    for (int m = 0; m < NDM; m += 4) {
        float4 w4 = *(const float4*)&wr[m];
        acc = fmaf(cf[m], w4.x, acc);
        acc = fmaf(cf[m + 1], w4.y, acc);
        acc = fmaf(cf[m + 2], w4.z, acc);
        acc = fmaf(cf[m + 3], w4.w, acc);
    }
    out[b * NDM + o] = acc;
}

// ---------------------------------------------------------------------------
extern "C" void kernel_launch(void* const* d_in, const int* in_sizes, int n_in,
                              void* d_out, int out_size)
{
    const float* Q   = (const float*)d_in[0];
    const float* K   = (const float*)d_in[1];
    const float* V   = (const float*)d_in[2];
    const float* Wq  = (const float*)d_in[3];
    const float* bq  = (const float*)d_in[4];
    const float* Wk  = (const float*)d_in[5];
    const float* bk  = (const float*)d_in[6];
    const float* Wv  = (const float*)d_in[7];
    const float* bv  = (const float*)d_in[8];
    const float* Wo  = (const float*)d_in[9];
    const float* bo  = (const float*)d_in[10];
    const int*   idx = (const int*)d_in[11];
    float* out = (float*)d_out;

    // 1) Q/K/V projections (fp32)
    {
        dim3 grid(NDM / 128, (NB * NL) / 128, 3);
        proj_kernel<<<grid, 256>>>(Q, K, V, Wq, bq, Wk, bk, Wv, bv);
    }
    // 2) Sparsity scores M
    {
        dim3 grid(NL / 256, NBH);
        m_kernel<<<grid, 256>>>(idx);
    }
    // 3) Top-45 selection (+ g_ctx zero)
    topk_kernel<<<NBH, 256>>>();
    // 4) Sparse attention
    {
        dim3 grid(NU, NBH);
        attn_kernel<<<grid, 256>>>();
    }
    // 5) Output projection
    {
        dim3 grid(NDM / 256, NB);
        outproj_kernel<<<grid, 256>>>(Wo, bo, out);
    }
}

// round 15
// speedup vs baseline: 1.0012x; 1.0012x over previous
#include <cuda_runtime.h>
#include <math.h>

#define NB   8
#define NL   4096
#define NDM  1024
#define NH   16
#define NDH  64
#define NU   45
#define NBH  (NB*NH)

// Scratch (device globals — allocation-free rule)
__device__ float g_q[(size_t)NBH*NL*NDH];   // [b][h][l][d]
__device__ float g_k[(size_t)NBH*NL*NDH];
__device__ float g_v[(size_t)NBH*NL*NDH];
__device__ float g_M[(size_t)NBH*NL];
__device__ int   g_top[NBH*NU];
__device__ float g_ctx[NBH*NDH];

// ---------------------------------------------------------------------------
// Projection SGEMM: C[r, j] = sum_c In[r,c] * W[j,c] + bias[j]
// In: (32768 x 1024) row-major, W: (1024 x 1024) row-major ("out" dim first).
// Output scattered into [b][h][l][d] layout. 128x128 tile, 16 k-step,
// 256 threads, 8x8 register micro-tile.
// blockIdx.z selects which projection (0=q,1=k,2=v).
// ---------------------------------------------------------------------------
__global__ __launch_bounds__(256, 2)
void proj_kernel(const float* __restrict__ Qin, const float* __restrict__ Kin,
                 const float* __restrict__ Vin,
                 const float* __restrict__ Wq, const float* __restrict__ bq,
                 const float* __restrict__ Wk, const float* __restrict__ bk,
                 const float* __restrict__ Wv, const float* __restrict__ bv)
{
    const float* In; const float* W; const float* bias; float* Out;
    if (blockIdx.z == 0)      { In = Qin; W = Wq; bias = bq; Out = g_q; }
    else if (blockIdx.z == 1) { In = Kin; W = Wk; bias = bk; Out = g_k; }
    else                      { In = Vin; W = Wv; bias = bv; Out = g_v; }

    __shared__ float As[16][128];
    __shared__ float Bs[16][128];

    const int row0 = blockIdx.y * 128;
    const int col0 = blockIdx.x * 128;
    const int tid  = threadIdx.x;
    const int ty   = tid >> 4;     // 0..15
    const int tx   = tid & 15;     // 0..15

    float acc[8][8];
#pragma unroll
    for (int i = 0; i < 8; i++)
#pragma unroll
        for (int j = 0; j < 8; j++) acc[i][j] = 0.f;

    for (int c0 = 0; c0 < NDM; c0 += 16) {
        // Load 128x16 tiles of A and W (transposed into smem: [c][row])
#pragma unroll
        for (int it = 0; it < 2; it++) {
            int s  = tid + it * 256;        // 0..511
            int r  = s >> 2;                // 0..127
            int cv = (s & 3) * 4;           // 0,4,8,12
            float4 a = *(const float4*)&In[(size_t)(row0 + r) * NDM + c0 + cv];
            As[cv + 0][r] = a.x; As[cv + 1][r] = a.y;
            As[cv + 2][r] = a.z; As[cv + 3][r] = a.w;
            float4 b = *(const float4*)&W[(size_t)(col0 + r) * NDM + c0 + cv];
            Bs[cv + 0][r] = b.x; Bs[cv + 1][r] = b.y;
            Bs[cv + 2][r] = b.z; Bs[cv + 3][r] = b.w;
        }
        __syncthreads();

#pragma unroll
        for (int c = 0; c < 16; c++) {
            float4 a0 = *(const float4*)&As[c][ty * 8];
            float4 a1 = *(const float4*)&As[c][ty * 8 + 4];
            float4 b0 = *(const float4*)&Bs[c][tx * 8];
            float4 b1 = *(const float4*)&Bs[c][tx * 8 + 4];
            float av[8] = {a0.x, a0.y, a0.z, a0.w, a1.x, a1.y, a1.z, a1.w};
            float bv2[8] = {b0.x, b0.y, b0.z, b0.w, b1.x, b1.y, b1.z, b1.w};
#pragma unroll
            for (int i = 0; i < 8; i++)
#pragma unroll
                for (int j = 0; j < 8; j++)
                    acc[i][j] = fmaf(av[i], bv2[j], acc[i][j]);
        }
        __syncthreads();
    }

    // Epilogue: scatter into [b][h][l][d]
#pragma unroll
    for (int i = 0; i < 8; i++) {
        int r = row0 + ty * 8 + i;
        int b_ = r >> 12;            // /4096
        int l  = r & (NL - 1);
#pragma unroll
        for (int j = 0; j < 8; j++) {
            int col = col0 + tx * 8 + j;
            int h = col >> 6;
            int d = col & 63;
            Out[(((size_t)(b_ * NH + h)) * NL + l) * NDH + d] = acc[i][j] + bias[col];
        }
    }
}

// ---------------------------------------------------------------------------
// M kernel: per (b,h,query) compute qk against 45 sampled keys, M = max - mean
// ---------------------------------------------------------------------------
__global__ __launch_bounds__(256)
void m_kernel(const int* __restrict__ idx)
{
    const int bh = blockIdx.y;
    __shared__ float ks[NU][NDH];

    for (int t = threadIdx.x; t < NU * NDH; t += 256) {
        int j = t >> 6, d = t & 63;
        int key = idx[j];
        ks[j][d] = g_k[((size_t)bh * NL + key) * NDH + d];
    }
    __syncthreads();

    const int i = blockIdx.x * 256 + threadIdx.x;
    const float* qp = &g_q[((size_t)bh * NL + i) * NDH];
    float q[NDH];
#pragma unroll
    for (int d = 0; d < NDH; d += 4) {
        float4 t4 = *(const float4*)&qp[d];
        q[d] = t4.x; q[d + 1] = t4.y; q[d + 2] = t4.z; q[d + 3] = t4.w;
    }

    float mx = -INFINITY, sum = 0.f;
    for (int j = 0; j < NU; j++) {
        float s = 0.f;
#pragma unroll
        for (int d = 0; d < NDH; d++) s = fmaf(q[d], ks[j][d], s);
        mx = fmaxf(mx, s);
        sum += s;
    }
    g_M[(size_t)bh * NL + i] = mx - sum * (1.0f / NU);
}

// ---------------------------------------------------------------------------
// Top-45 per (b,h): iterative argmax over 4096 with lowest-index tie break.
// Also zeroes g_ctx for this (b,h).
// ---------------------------------------------------------------------------
__global__ __launch_bounds__(256)
void topk_kernel()
{
    const int bh = blockIdx.x;
    const int tid = threadIdx.x;
    __shared__ float sm[NL];
    __shared__ float rv[256];
    __shared__ int   ri[256];

    if (tid < NDH) g_ctx[bh * NDH + tid] = 0.f;

    for (int t = tid; t < NL; t += 256) sm[t] = g_M[(size_t)bh * NL + t];
    __syncthreads();

    for (int it = 0; it < NU; it++) {
        float best = -INFINITY;
        int bidx = NL;
        for (int t = tid; t < NL; t += 256) {
            float v = sm[t];
            if (v > best) { best = v; bidx = t; }
        }
        rv[tid] = best; ri[tid] = bidx;
        __syncthreads();
        for (int off = 128; off > 0; off >>= 1) {
            if (tid < off) {
                float v2 = rv[tid + off]; int i2 = ri[tid + off];
                if (v2 > rv[tid] || (v2 == rv[tid] && i2 < ri[tid])) {
                    rv[tid] = v2; ri[tid] = i2;
                }
            }
            __syncthreads();
        }
        if (tid == 0) {
            g_top[bh * NU + it] = ri[0];
            sm[ri[0]] = -INFINITY;
        }
        __syncthreads();
    }
}

// ---------------------------------------------------------------------------
// Attention kernel: one block per (b,h,u). Full softmax over 4096 keys,
// ctx accumulated into g_ctx (sum with 1/45 factor).
// ---------------------------------------------------------------------------
__global__ __launch_bounds__(256)
void attn_kernel()
{
    const int bh = blockIdx.y;
    const int u  = blockIdx.x;
    const int tid = threadIdx.x;

    __shared__ float sc[NL];     // 16 KB
    __shared__ float qs[NDH];
    __shared__ float red[256];

    const int qi = g_top[bh * NU + u];
    if (tid < NDH) qs[tid] = g_q[((size_t)bh * NL + qi) * NDH + tid];
    __syncthreads();

    const float* kb = &g_k[(size_t)bh * NL * NDH];
    for (int key = tid; key < NL; key += 256) {
        const float* kr = &kb[key * NDH];
        float s = 0.f;
#pragma unroll
        for (int d = 0; d < NDH; d += 4) {
            float4 k4 = *(const float4*)&kr[d];
            s = fmaf(k4.x, qs[d], s);
            s = fmaf(k4.y, qs[d + 1], s);
            s = fmaf(k4.z, qs[d + 2], s);
            s = fmaf(k4.w, qs[d + 3], s);
        }
        sc[key] = s * 0.125f;    // 1/sqrt(64)
    }
    __syncthreads();

    // max
    float mx = -INFINITY;
    for (int key = tid; key < NL; key += 256) mx = fmaxf(mx, sc[key]);
    red[tid] = mx; __syncthreads();
    for (int off = 128; off > 0; off >>= 1) {
        if (tid < off) red[tid] = fmaxf(red[tid], red[tid + off]);
        __syncthreads();
    }
    mx = red[0];
    __syncthreads();

    // exp + sum
    float sum = 0.f;
    for (int key = tid; key < NL; key += 256) {
        float e = __expf(sc[key] - mx);
        sc[key] = e;
        sum += e;
    }
    red[tid] = sum; __syncthreads();
    for (int off = 128; off > 0; off >>= 1) {
        if (tid < off) red[tid] += red[tid + off];
        __syncthreads();
    }
    const float inv = 1.0f / red[0];
    __syncthreads();

    // ctx: thread (g, d), g in 0..3, d in 0..63
    const int d = tid & 63;
    const int g = tid >> 6;
    const float* vb = &g_v[(size_t)bh * NL * NDH];
    float acc = 0.f;
    for (int key = g; key < NL; key += 4)
        acc = fmaf(sc[key], vb[(size_t)key * NDH + d], acc);
    red[tid] = acc;
    __syncthreads();
    if (g == 0) {
        float tot = red[d] + red[64 + d] + red[128 + d] + red[192 + d];
        atomicAdd(&g_ctx[bh * NDH + d], tot * inv * (1.0f / NU));
    }
}

// ---------------------------------------------------------------------------
// Output projection: out[b,o] = sum_m ctx_flat[b,m] * Wo[o,m] + bo[o]
// ctx_flat[b, d*16 + h] = g_ctx[(b*16+h)*64 + d]   (transpose(0,2,1).reshape)
// ---------------------------------------------------------------------------
__global__ __launch_bounds__(256)
void outproj_kernel(const float* __restrict__ Wo, const float* __restrict__ bo,
                    float* __restrict__ out)
{
    const int b = blockIdx.y;
    const int o = blockIdx.x * 256 + threadIdx.x;
    __shared__ float cf[NDM];

    for (int t = threadIdx.x; t < NDM; t += 256) {
        int d = t >> 4;      // m = d*16 + h
        int h = t & 15;
        cf[t] = g_ctx[(b * NH + h) * NDH + d];
    }
    __syncthreads();

    float acc = bo[o];
    const float* wr = &Wo[(size_t)o * NDM];
#pragma unroll 4
    for (int m = 0; m < NDM; m += 4) {
        float4 w4 = *(const float4*)&wr[m];
        acc = fmaf(cf[m], w4.x, acc);
        acc = fmaf(cf[m + 1], w4.y, acc);
        acc = fmaf(cf[m + 2], w4.z, acc);
        acc = fmaf(cf[m + 3], w4.w, acc);
    }
    out[b * NDM + o] = acc;
}

// ---------------------------------------------------------------------------
extern "C" void kernel_launch(void* const* d_in, const int* in_sizes, int n_in,
                              void* d_out, int out_size)
{
    const float* Q   = (const float*)d_in[0];
    const float* K   = (const float*)d_in[1];
    const float* V   = (const float*)d_in[2];
    const float* Wq  = (const float*)d_in[3];
    const float* bq  = (const float*)d_in[4];
    const float* Wk  = (const float*)d_in[5];
    const float* bk  = (const float*)d_in[6];
    const float* Wv  = (const float*)d_in[7];
    const float* bv  = (const float*)d_in[8];
    const float* Wo  = (const float*)d_in[9];
    const float* bo  = (const float*)d_in[10];
    const int*   idx = (const int*)d_in[11];
    float* out = (float*)d_out;

    // 1) Q/K/V projections (fp32)
    {
        dim3 grid(NDM / 128, (NB * NL) / 128, 3);
        proj_kernel<<<grid, 256>>>(Q, K, V, Wq, bq, Wk, bk, Wv, bv);
    }
    // 2) Sparsity scores M
    {
        dim3 grid(NL / 256, NBH);
        m_kernel<<<grid, 256>>>(idx);
    }
    // 3) Top-45 selection (+ g_ctx zero)
    topk_kernel<<<NBH, 256>>>();
    // 4) Sparse attention
    {
        dim3 grid(NU, NBH);
        attn_kernel<<<grid, 256>>>();
    }
    // 5) Output projection
    {
        dim3 grid(NDM / 256, NB);
        outproj_kernel<<<grid, 256>>>(Wo, bo, out);
    }
}